// round 2
// baseline (speedup 1.0000x reference)
#include <cuda_runtime.h>
#include <math.h>

// Problem dims (fixed by the reference)
#define Bz      8
#define Tz      4096
#define Cz      256
#define HIDz    1024
#define BTz     (Bz*Tz)          // 32768 tokens
#define CHUNK   128
#define NCHUNK  (Tz/CHUNK)       // 32

// ---------------- scratch (static __device__, no allocs) ----------------
__device__ float g_h  [(size_t)BTz*Cz];    // h (LN1), later reused for sr*y
__device__ float g_k  [(size_t)BTz*Cz];
__device__ float g_v  [(size_t)BTz*Cz];
__device__ float g_sr [(size_t)BTz*Cz];    // sigmoid(h@Wr), later rr gate
__device__ float g_y  [(size_t)BTz*Cz];
__device__ float g_h2 [(size_t)BTz*Cz];
__device__ float g_kk [(size_t)BTz*HIDz];  // FFN hidden (128 MB)
__device__ float g_cA [Bz*Cz*NCHUNK];      // chunk partial numer sums
__device__ float g_cB [Bz*Cz*NCHUNK];      // chunk partial denom sums
__device__ float g_a0 [Bz*Cz*NCHUNK];      // carry-in numer per chunk
__device__ float g_b0 [Bz*Cz*NCHUNK];      // carry-in denom per chunk

// ---------------- LayerNorm: one block (256 thr) per token ----------------
__global__ void ln_kernel(const float* __restrict__ x,
                          const float* __restrict__ g,
                          const float* __restrict__ b,
                          float* __restrict__ out)
{
    __shared__ float red[16];
    size_t base = (size_t)blockIdx.x * Cz;
    int c = threadIdx.x;
    float val = x[base + c];
    float s = val, s2 = val * val;
    #pragma unroll
    for (int off = 16; off; off >>= 1) {
        s  += __shfl_xor_sync(0xffffffffu, s,  off);
        s2 += __shfl_xor_sync(0xffffffffu, s2, off);
    }
    int warp = c >> 5, lane = c & 31;
    if (lane == 0) { red[warp] = s; red[8 + warp] = s2; }
    __syncthreads();
    float ts = 0.f, ts2 = 0.f;
    #pragma unroll
    for (int i = 0; i < 8; i++) { ts += red[i]; ts2 += red[8 + i]; }
    float m   = ts  * (1.0f / Cz);
    float var = ts2 * (1.0f / Cz) - m * m;
    out[base + c] = (val - m) * rsqrtf(var + 1e-5f) * g[c] + b[c];
}

// ---------------- elementwise multiply (sr * y) ----------------
__global__ void mul_kernel(const float* __restrict__ a,
                           const float* __restrict__ b,
                           float* __restrict__ o)
{
    size_t i = (size_t)blockIdx.x * blockDim.x + threadIdx.x;
    o[i] = a[i] * b[i];
}

// ---------------- fp32 GEMM: out[M,N] = A[M,K] @ W[K,N], M = BTz ----------------
// BM=128, BN=64, BK=16, 256 threads, each computes 8x4 outputs.
// mode: 0 plain, 1 sigmoid, 2 relu^2, 3 res+acc, 4 res+gate*acc
#define GBM 128
#define GBN 64
#define GBK 16
__global__ void gemm_kernel(const float* __restrict__ A,
                            const float* __restrict__ W,
                            float* __restrict__ out,
                            const float* __restrict__ res,
                            const float* __restrict__ gate,
                            int K, int N, int mode)
{
    __shared__ float sA[GBK][GBM + 4];
    __shared__ float sB[GBK][GBN];

    int tid = threadIdx.x;
    int block_row = blockIdx.x * GBM;
    int block_col = blockIdx.y * GBN;
    int tx = tid & 15;   // col group (x4)
    int ty = tid >> 4;   // row group (x8)

    float acc[8][4];
    #pragma unroll
    for (int i = 0; i < 8; i++)
        #pragma unroll
        for (int j = 0; j < 4; j++) acc[i][j] = 0.f;

    for (int k0 = 0; k0 < K; k0 += GBK) {
        // load A tile 128x16 (transposed into sA[k][m]): 512 float4, 2/thread
        #pragma unroll
        for (int l = 0; l < 2; l++) {
            int idx = tid + l * 256;
            int r = idx >> 2;
            int cc = (idx & 3) * 4;
            float4 a4 = *(const float4*)(A + (size_t)(block_row + r) * K + k0 + cc);
            sA[cc + 0][r] = a4.x; sA[cc + 1][r] = a4.y;
            sA[cc + 2][r] = a4.z; sA[cc + 3][r] = a4.w;
        }
        // load W tile 16x64: 256 float4, 1/thread
        {
            int r = tid >> 4;
            int cc = (tid & 15) * 4;
            float4 b4 = *(const float4*)(W + (size_t)(k0 + r) * N + block_col + cc);
            *(float4*)&sB[r][cc] = b4;
        }
        __syncthreads();
        #pragma unroll
        for (int kk = 0; kk < GBK; kk++) {
            float ra[8], rb[4];
            #pragma unroll
            for (int i = 0; i < 8; i++) ra[i] = sA[kk][ty * 8 + i];
            #pragma unroll
            for (int j = 0; j < 4; j++) rb[j] = sB[kk][tx * 4 + j];
            #pragma unroll
            for (int i = 0; i < 8; i++)
                #pragma unroll
                for (int j = 0; j < 4; j++) acc[i][j] += ra[i] * rb[j];
        }
        __syncthreads();
    }

    #pragma unroll
    for (int i = 0; i < 8; i++) {
        int row = block_row + ty * 8 + i;
        #pragma unroll
        for (int j = 0; j < 4; j++) {
            int col = block_col + tx * 4 + j;
            size_t o = (size_t)row * N + col;
            float vv = acc[i][j];
            if (mode == 1) {
                vv = 1.0f / (1.0f + __expf(-vv));
            } else if (mode == 2) {
                float r2 = fmaxf(vv, 0.f);
                vv = r2 * r2;
            } else if (mode == 3) {
                vv = res[o] + vv;
            } else if (mode == 4) {
                vv = res[o] + gate[o] * vv;
            }
            out[o] = vv;
        }
    }
}

// ---------------- WKV (direct linear recurrence, chunked 3-pass) ----------------
// w = decay[c]/T, u = first[c]/T.  State: a = sum e^{w*(t-1-i)+k_i} v_i, b same w/o v.
// y_t = (a + e^{u+k_t} v_t) / (b + e^{u+k_t});  a' = e^w a + e^{k_t} v_t;  b' = e^w b + e^{k_t}

// Pass 1: per-chunk local sums (zero carry-in)
__global__ void wkv_pass1(const float* __restrict__ k, const float* __restrict__ v,
                          const float* __restrict__ decay)
{
    int b  = blockIdx.x >> 5;          // /NCHUNK
    int ch = blockIdx.x & (NCHUNK - 1);
    int c  = threadIdx.x;
    float w  = decay[c] * (1.0f / Tz);
    float ew = __expf(w);
    size_t base = ((size_t)b * Tz + (size_t)ch * CHUNK) * Cz + c;
    float a = 0.f, bb = 0.f;
    #pragma unroll 4
    for (int i = 0; i < CHUNK; i++) {
        float ek = __expf(k[base + (size_t)i * Cz]);
        float vv = v[base + (size_t)i * Cz];
        a  = fmaf(ew, a,  ek * vv);
        bb = fmaf(ew, bb, ek);
    }
    int o = ch * (Bz * Cz) + b * Cz + c;
    g_cA[o] = a;
    g_cB[o] = bb;
}

// Pass 2: sequential scan over chunks per (b,c); stores carry-in state per chunk
__global__ void wkv_pass2(const float* __restrict__ decay)
{
    int idx = blockIdx.x * blockDim.x + threadIdx.x;  // b*Cz + c, 2048 total
    int c = idx & (Cz - 1);
    float w   = decay[c] * (1.0f / Tz);
    float ewL = __expf(w * CHUNK);
    float a = 0.f, bb = 0.f;
    #pragma unroll
    for (int ch = 0; ch < NCHUNK; ch++) {
        int o = ch * (Bz * Cz) + idx;
        g_a0[o] = a;
        g_b0[o] = bb;
        a  = fmaf(ewL, a,  g_cA[o]);
        bb = fmaf(ewL, bb, g_cB[o]);
    }
}

// Pass 3: recompute with carry-in, emit y
__global__ void wkv_pass3(const float* __restrict__ k, const float* __restrict__ v,
                          const float* __restrict__ decay, const float* __restrict__ first,
                          float* __restrict__ y)
{
    int b  = blockIdx.x >> 5;
    int ch = blockIdx.x & (NCHUNK - 1);
    int c  = threadIdx.x;
    float w  = decay[c] * (1.0f / Tz);
    float u  = first[c] * (1.0f / Tz);
    float ew = __expf(w);
    float eu = __expf(u);
    int co = ch * (Bz * Cz) + b * Cz + c;
    float a  = g_a0[co];
    float bb = g_b0[co];
    size_t base = ((size_t)b * Tz + (size_t)ch * CHUNK) * Cz + c;
    #pragma unroll 4
    for (int i = 0; i < CHUNK; i++) {
        float kk = k[base + (size_t)i * Cz];
        float vv = v[base + (size_t)i * Cz];
        float ek = __expf(kk);
        float e2 = eu * ek;
        y[base + (size_t)i * Cz] = __fdividef(fmaf(e2, vv, a), bb + e2);
        a  = fmaf(ew, a,  ek * vv);
        bb = fmaf(ew, bb, ek);
    }
}

// ---------------- launch ----------------
extern "C" void kernel_launch(void* const* d_in, const int* in_sizes, int n_in,
                              void* d_out, int out_size)
{
    const float* x      = (const float*)d_in[0];
    const float* Wk     = (const float*)d_in[1];
    const float* Wv     = (const float*)d_in[2];
    const float* Wr     = (const float*)d_in[3];
    const float* Wo     = (const float*)d_in[4];
    const float* Wk_ffn = (const float*)d_in[5];
    const float* Wv_ffn = (const float*)d_in[6];
    const float* Wr_ffn = (const float*)d_in[7];
    const float* g1     = (const float*)d_in[8];
    const float* b1     = (const float*)d_in[9];
    const float* g2     = (const float*)d_in[10];
    const float* b2     = (const float*)d_in[11];
    const float* decay  = (const float*)d_in[12];
    const float* first  = (const float*)d_in[13];
    float* out = (float*)d_out;

    float *h, *kb, *vb, *sr, *yb, *h2, *kkb;
    cudaGetSymbolAddress((void**)&h,   g_h);
    cudaGetSymbolAddress((void**)&kb,  g_k);
    cudaGetSymbolAddress((void**)&vb,  g_v);
    cudaGetSymbolAddress((void**)&sr,  g_sr);
    cudaGetSymbolAddress((void**)&yb,  g_y);
    cudaGetSymbolAddress((void**)&h2,  g_h2);
    cudaGetSymbolAddress((void**)&kkb, g_kk);

    dim3 g256(BTz / GBM, Cz   / GBN);   // N=256
    dim3 g1024(BTz / GBM, HIDz / GBN);  // N=1024

    // ---- SpatialMix ----
    ln_kernel<<<BTz, Cz>>>(x, g1, b1, h);
    gemm_kernel<<<g256, 256>>>(h, Wk, kb, nullptr, nullptr, Cz, Cz, 0);
    gemm_kernel<<<g256, 256>>>(h, Wv, vb, nullptr, nullptr, Cz, Cz, 0);
    gemm_kernel<<<g256, 256>>>(h, Wr, sr, nullptr, nullptr, Cz, Cz, 1);

    wkv_pass1<<<Bz * NCHUNK, Cz>>>(kb, vb, decay);
    wkv_pass2<<<Bz, Cz>>>(decay);
    wkv_pass3<<<Bz * NCHUNK, Cz>>>(kb, vb, decay, first, yb);

    mul_kernel<<<(BTz * Cz) / 256, 256>>>(sr, yb, h);             // h := sr*y
    gemm_kernel<<<g256, 256>>>(h, Wo, out, x, nullptr, Cz, Cz, 3); // out = x + (sr*y)@Wo

    // ---- ChannelMix ----
    ln_kernel<<<BTz, Cz>>>(out, g2, b2, h2);
    gemm_kernel<<<g1024, 256>>>(h2, Wk_ffn, kkb, nullptr, nullptr, Cz, HIDz, 2); // relu^2
    gemm_kernel<<<g256, 256>>>(h2, Wr_ffn, sr, nullptr, nullptr, Cz, Cz, 1);     // rr gate
    gemm_kernel<<<g256, 256>>>(kkb, Wv_ffn, out, out, sr, HIDz, Cz, 4);          // out += rr*(kk@Wv)
    (void)in_sizes; (void)n_in; (void)out_size;
}

// round 3
// speedup vs baseline: 2.0988x; 2.0988x over previous
#include <cuda_runtime.h>
#include <cuda_bf16.h>
#include <math.h>

// Problem dims (fixed by the reference)
#define Bz      8
#define Tz      4096
#define Cz      256
#define HIDz    1024
#define BTz     (Bz*Tz)          // 32768 tokens
#define CHUNK   128
#define NCHUNK  (Tz/CHUNK)       // 32

typedef unsigned short bf16r;    // raw bf16 bits

// ---------------- scratch (static __device__, no allocs) ----------------
__device__ float g_k  [(size_t)BTz*Cz];
__device__ float g_v  [(size_t)BTz*Cz];
__device__ float g_sr [(size_t)BTz*Cz];
__device__ float g_y  [(size_t)BTz*Cz];
__device__ bf16r g_hb [(size_t)BTz*Cz];    // bf16 LN1 out / sr*y
__device__ bf16r g_h2b[(size_t)BTz*Cz];    // bf16 LN2 out
__device__ bf16r g_kkb[(size_t)BTz*HIDz];  // bf16 FFN hidden
__device__ float g_cA [Bz*Cz*NCHUNK];
__device__ float g_cB [Bz*Cz*NCHUNK];
__device__ float g_a0 [Bz*Cz*NCHUNK];
__device__ float g_b0 [Bz*Cz*NCHUNK];
// bf16 weights
__device__ bf16r g_wk [Cz*Cz];
__device__ bf16r g_wv [Cz*Cz];
__device__ bf16r g_wr [Cz*Cz];
__device__ bf16r g_wo [Cz*Cz];
__device__ bf16r g_wkf[Cz*HIDz];
__device__ bf16r g_wvf[HIDz*Cz];
__device__ bf16r g_wrf[Cz*Cz];

__device__ __forceinline__ bf16r f2b_one(float f) {
    __nv_bfloat16 b = __float2bfloat16(f);
    return *(bf16r*)&b;
}

// ---------------- fp32 -> bf16 convert ----------------
__global__ void f2b_kernel(const float* __restrict__ a, bf16r* __restrict__ o, int n)
{
    int i = blockIdx.x * 256 + threadIdx.x;
    if (i < n) o[i] = f2b_one(a[i]);
}

// ---------------- LayerNorm: one block (256 thr) per token, bf16 out ----------------
__global__ void ln_kernel(const float* __restrict__ x,
                          const float* __restrict__ g,
                          const float* __restrict__ b,
                          bf16r* __restrict__ out)
{
    __shared__ float red[16];
    size_t base = (size_t)blockIdx.x * Cz;
    int c = threadIdx.x;
    float val = x[base + c];
    float s = val, s2 = val * val;
    #pragma unroll
    for (int off = 16; off; off >>= 1) {
        s  += __shfl_xor_sync(0xffffffffu, s,  off);
        s2 += __shfl_xor_sync(0xffffffffu, s2, off);
    }
    int warp = c >> 5, lane = c & 31;
    if (lane == 0) { red[warp] = s; red[8 + warp] = s2; }
    __syncthreads();
    float ts = 0.f, ts2 = 0.f;
    #pragma unroll
    for (int i = 0; i < 8; i++) { ts += red[i]; ts2 += red[8 + i]; }
    float m   = ts  * (1.0f / Cz);
    float var = ts2 * (1.0f / Cz) - m * m;
    out[base + c] = f2b_one((val - m) * rsqrtf(var + 1e-5f) * g[c] + b[c]);
}

// ---------------- elementwise multiply (sr * y) -> bf16 ----------------
__global__ void mul_kernel(const float* __restrict__ a,
                           const float* __restrict__ b,
                           bf16r* __restrict__ o)
{
    size_t i = (size_t)blockIdx.x * blockDim.x + threadIdx.x;
    o[i] = f2b_one(a[i] * b[i]);
}

// ---------------- bf16 tensor-core GEMM: out[M,N] = A[M,K] @ W[K,N] ----------------
// BM=128, BN=64, BK=32, 256 threads = 8 warps (4x2), warp tile 32x32.
// mma.sync.aligned.m16n8k16.row.col.f32.bf16.bf16.f32
// mode: 0 plain, 1 sigmoid, 2 relu^2, 3 res+acc, 4 res+gate*acc
#define LDA 40
#define LDB 40
template<bool OUT_BF16>
__global__ void gemm_bf16_kernel(const bf16r* __restrict__ A,
                                 const bf16r* __restrict__ Bw,
                                 void* __restrict__ outv,
                                 const float* __restrict__ res,
                                 const float* __restrict__ gate,
                                 int K, int N, int mode)
{
    __shared__ bf16r sA[128 * LDA];
    __shared__ bf16r sB[64  * LDB];

    int tid  = threadIdx.x;
    int lane = tid & 31;
    int warp = tid >> 5;
    int wm = (warp & 3) * 32;
    int wn = (warp >> 2) * 32;
    int blockRow = blockIdx.x * 128;
    int blockCol = blockIdx.y * 64;

    float acc[2][4][4];
    #pragma unroll
    for (int i = 0; i < 2; i++)
        #pragma unroll
        for (int j = 0; j < 4; j++)
            #pragma unroll
            for (int l = 0; l < 4; l++) acc[i][j][l] = 0.f;

    for (int kb = 0; kb < K; kb += 32) {
        // A tile: 128 x 32 bf16 = 8KB, row-major, 16B chunks
        #pragma unroll
        for (int it = 0; it < 2; it++) {
            int idx = tid + it * 256;
            int row = idx >> 2, chunk = idx & 3;
            const uint4* gp = (const uint4*)(A + (size_t)(blockRow + row) * K + kb + chunk * 8);
            *(uint4*)(sA + row * LDA + chunk * 8) = *gp;
        }
        // B tile: 32 x 64 bf16, stored transposed sB[n][k]
        #pragma unroll
        for (int it = 0; it < 4; it++) {
            int p = tid + it * 256;
            int k = p >> 5;
            int n = (p & 31) * 2;
            unsigned int w = *(const unsigned int*)(Bw + (size_t)(kb + k) * N + blockCol + n);
            sB[n * LDB + k]       = (bf16r)(w & 0xFFFFu);
            sB[(n + 1) * LDB + k] = (bf16r)(w >> 16);
        }
        __syncthreads();

        #pragma unroll
        for (int k16 = 0; k16 < 2; k16++) {
            int koff = k16 * 16;
            unsigned int afr[2][4], bfr[4][2];
            #pragma unroll
            for (int sm = 0; sm < 2; sm++) {
                const bf16r* p = sA + (wm + sm * 16 + (lane >> 2)) * LDA + koff + (lane & 3) * 2;
                afr[sm][0] = *(const unsigned int*)(p);
                afr[sm][1] = *(const unsigned int*)(p + 8 * LDA);
                afr[sm][2] = *(const unsigned int*)(p + 8);
                afr[sm][3] = *(const unsigned int*)(p + 8 * LDA + 8);
            }
            #pragma unroll
            for (int sn = 0; sn < 4; sn++) {
                const bf16r* p = sB + (wn + sn * 8 + (lane >> 2)) * LDB + koff + (lane & 3) * 2;
                bfr[sn][0] = *(const unsigned int*)(p);
                bfr[sn][1] = *(const unsigned int*)(p + 8);
            }
            #pragma unroll
            for (int sm = 0; sm < 2; sm++)
                #pragma unroll
                for (int sn = 0; sn < 4; sn++) {
                    asm volatile(
                        "mma.sync.aligned.m16n8k16.row.col.f32.bf16.bf16.f32 "
                        "{%0,%1,%2,%3}, {%4,%5,%6,%7}, {%8,%9}, {%0,%1,%2,%3};"
                        : "+f"(acc[sm][sn][0]), "+f"(acc[sm][sn][1]),
                          "+f"(acc[sm][sn][2]), "+f"(acc[sm][sn][3])
                        : "r"(afr[sm][0]), "r"(afr[sm][1]), "r"(afr[sm][2]), "r"(afr[sm][3]),
                          "r"(bfr[sn][0]), "r"(bfr[sn][1]));
                }
        }
        __syncthreads();
    }

    // Epilogue
    #pragma unroll
    for (int sm = 0; sm < 2; sm++) {
        #pragma unroll
        for (int sn = 0; sn < 4; sn++) {
            int r0 = blockRow + wm + sm * 16 + (lane >> 2);
            int cc = blockCol + wn + sn * 8 + (lane & 3) * 2;
            #pragma unroll
            for (int half = 0; half < 2; half++) {
                int row = r0 + half * 8;
                size_t o = (size_t)row * N + cc;
                float v0 = acc[sm][sn][half * 2 + 0];
                float v1 = acc[sm][sn][half * 2 + 1];
                if (mode == 1) {
                    v0 = 1.0f / (1.0f + __expf(-v0));
                    v1 = 1.0f / (1.0f + __expf(-v1));
                } else if (mode == 2) {
                    float a0 = fmaxf(v0, 0.f), a1 = fmaxf(v1, 0.f);
                    v0 = a0 * a0; v1 = a1 * a1;
                } else if (mode == 3) {
                    v0 += res[o]; v1 += res[o + 1];
                } else if (mode == 4) {
                    v0 = res[o]     + gate[o]     * v0;
                    v1 = res[o + 1] + gate[o + 1] * v1;
                }
                if (OUT_BF16) {
                    unsigned int pk = ((unsigned int)f2b_one(v1) << 16) | f2b_one(v0);
                    *(unsigned int*)((bf16r*)outv + o) = pk;
                } else {
                    *(float2*)((float*)outv + o) = make_float2(v0, v1);
                }
            }
        }
    }
}

// ---------------- WKV (direct linear recurrence, chunked 3-pass) ----------------
__global__ void wkv_pass1(const float* __restrict__ k, const float* __restrict__ v,
                          const float* __restrict__ decay)
{
    int b  = blockIdx.x >> 5;
    int ch = blockIdx.x & (NCHUNK - 1);
    int c  = threadIdx.x;
    float w  = decay[c] * (1.0f / Tz);
    float ew = __expf(w);
    size_t base = ((size_t)b * Tz + (size_t)ch * CHUNK) * Cz + c;
    float a = 0.f, bb = 0.f;
    #pragma unroll 4
    for (int i = 0; i < CHUNK; i++) {
        float ek = __expf(k[base + (size_t)i * Cz]);
        float vv = v[base + (size_t)i * Cz];
        a  = fmaf(ew, a,  ek * vv);
        bb = fmaf(ew, bb, ek);
    }
    int o = ch * (Bz * Cz) + b * Cz + c;
    g_cA[o] = a;
    g_cB[o] = bb;
}

__global__ void wkv_pass2(const float* __restrict__ decay)
{
    int idx = blockIdx.x * blockDim.x + threadIdx.x;
    int c = idx & (Cz - 1);
    float w   = decay[c] * (1.0f / Tz);
    float ewL = __expf(w * CHUNK);
    float a = 0.f, bb = 0.f;
    #pragma unroll
    for (int ch = 0; ch < NCHUNK; ch++) {
        int o = ch * (Bz * Cz) + idx;
        g_a0[o] = a;
        g_b0[o] = bb;
        a  = fmaf(ewL, a,  g_cA[o]);
        bb = fmaf(ewL, bb, g_cB[o]);
    }
}

__global__ void wkv_pass3(const float* __restrict__ k, const float* __restrict__ v,
                          const float* __restrict__ decay, const float* __restrict__ first,
                          float* __restrict__ y)
{
    int b  = blockIdx.x >> 5;
    int ch = blockIdx.x & (NCHUNK - 1);
    int c  = threadIdx.x;
    float w  = decay[c] * (1.0f / Tz);
    float u  = first[c] * (1.0f / Tz);
    float ew = __expf(w);
    float eu = __expf(u);
    int co = ch * (Bz * Cz) + b * Cz + c;
    float a  = g_a0[co];
    float bb = g_b0[co];
    size_t base = ((size_t)b * Tz + (size_t)ch * CHUNK) * Cz + c;
    #pragma unroll 4
    for (int i = 0; i < CHUNK; i++) {
        float kk = k[base + (size_t)i * Cz];
        float vv = v[base + (size_t)i * Cz];
        float ek = __expf(kk);
        float e2 = eu * ek;
        y[base + (size_t)i * Cz] = __fdividef(fmaf(e2, vv, a), bb + e2);
        a  = fmaf(ew, a,  ek * vv);
        bb = fmaf(ew, bb, ek);
    }
}

// ---------------- launch ----------------
extern "C" void kernel_launch(void* const* d_in, const int* in_sizes, int n_in,
                              void* d_out, int out_size)
{
    const float* x      = (const float*)d_in[0];
    const float* Wk     = (const float*)d_in[1];
    const float* Wv     = (const float*)d_in[2];
    const float* Wr     = (const float*)d_in[3];
    const float* Wo     = (const float*)d_in[4];
    const float* Wk_ffn = (const float*)d_in[5];
    const float* Wv_ffn = (const float*)d_in[6];
    const float* Wr_ffn = (const float*)d_in[7];
    const float* g1     = (const float*)d_in[8];
    const float* b1     = (const float*)d_in[9];
    const float* g2     = (const float*)d_in[10];
    const float* b2     = (const float*)d_in[11];
    const float* decay  = (const float*)d_in[12];
    const float* first  = (const float*)d_in[13];
    float* out = (float*)d_out;

    float *kb, *vb, *sr, *yb;
    bf16r *hb, *h2b, *kkb;
    bf16r *wk, *wv, *wr, *wo, *wkf, *wvf, *wrf;
    cudaGetSymbolAddress((void**)&kb,  g_k);
    cudaGetSymbolAddress((void**)&vb,  g_v);
    cudaGetSymbolAddress((void**)&sr,  g_sr);
    cudaGetSymbolAddress((void**)&yb,  g_y);
    cudaGetSymbolAddress((void**)&hb,  g_hb);
    cudaGetSymbolAddress((void**)&h2b, g_h2b);
    cudaGetSymbolAddress((void**)&kkb, g_kkb);
    cudaGetSymbolAddress((void**)&wk,  g_wk);
    cudaGetSymbolAddress((void**)&wv,  g_wv);
    cudaGetSymbolAddress((void**)&wr,  g_wr);
    cudaGetSymbolAddress((void**)&wo,  g_wo);
    cudaGetSymbolAddress((void**)&wkf, g_wkf);
    cudaGetSymbolAddress((void**)&wvf, g_wvf);
    cudaGetSymbolAddress((void**)&wrf, g_wrf);

    // weight conversions (small)
    f2b_kernel<<<(Cz*Cz   + 255)/256, 256>>>(Wk,     wk,  Cz*Cz);
    f2b_kernel<<<(Cz*Cz   + 255)/256, 256>>>(Wv,     wv,  Cz*Cz);
    f2b_kernel<<<(Cz*Cz   + 255)/256, 256>>>(Wr,     wr,  Cz*Cz);
    f2b_kernel<<<(Cz*Cz   + 255)/256, 256>>>(Wo,     wo,  Cz*Cz);
    f2b_kernel<<<(Cz*HIDz + 255)/256, 256>>>(Wk_ffn, wkf, Cz*HIDz);
    f2b_kernel<<<(HIDz*Cz + 255)/256, 256>>>(Wv_ffn, wvf, HIDz*Cz);
    f2b_kernel<<<(Cz*Cz   + 255)/256, 256>>>(Wr_ffn, wrf, Cz*Cz);

    dim3 g256(BTz / 128, Cz   / 64);   // (256, 4)
    dim3 g1024(BTz / 128, HIDz / 64);  // (256, 16)

    // ---- SpatialMix ----
    ln_kernel<<<BTz, Cz>>>(x, g1, b1, hb);
    gemm_bf16_kernel<false><<<g256, 256>>>(hb, wk, kb, nullptr, nullptr, Cz, Cz, 0);
    gemm_bf16_kernel<false><<<g256, 256>>>(hb, wv, vb, nullptr, nullptr, Cz, Cz, 0);
    gemm_bf16_kernel<false><<<g256, 256>>>(hb, wr, sr, nullptr, nullptr, Cz, Cz, 1);

    wkv_pass1<<<Bz * NCHUNK, Cz>>>(kb, vb, decay);
    wkv_pass2<<<Bz, Cz>>>(decay);
    wkv_pass3<<<Bz * NCHUNK, Cz>>>(kb, vb, decay, first, yb);

    mul_kernel<<<(BTz * Cz) / 256, 256>>>(sr, yb, hb);                       // hb := bf16(sr*y)
    gemm_bf16_kernel<false><<<g256, 256>>>(hb, wo, out, x, nullptr, Cz, Cz, 3);

    // ---- ChannelMix ----
    ln_kernel<<<BTz, Cz>>>(out, g2, b2, h2b);
    gemm_bf16_kernel<true ><<<g1024, 256>>>(h2b, wkf, kkb, nullptr, nullptr, Cz, HIDz, 2);
    gemm_bf16_kernel<false><<<g256, 256>>>(h2b, wrf, sr, nullptr, nullptr, Cz, Cz, 1);
    gemm_bf16_kernel<false><<<g256, 256>>>(kkb, wvf, out, out, sr, HIDz, Cz, 4);
    (void)in_sizes; (void)n_in; (void)out_size;
}

// round 4
// speedup vs baseline: 3.1499x; 1.5008x over previous
#include <cuda_runtime.h>
#include <cuda_bf16.h>
#include <math.h>

// Problem dims (fixed by the reference)
#define Bz      8
#define Tz      4096
#define Cz      256
#define HIDz    1024
#define BTz     (Bz*Tz)          // 32768 tokens
#define CHUNK   128
#define NCHUNK  (Tz/CHUNK)       // 32
#define NKVR    768              // k|v|r packed width
#define NFF1    1280             // ffn_k|ffn_r packed width

typedef unsigned short bf16r;    // raw bf16 bits

// ---------------- scratch (static __device__, no allocs) ----------------
__device__ float g_kvr[(size_t)BTz*NKVR];  // fp32 k|v|r(pre-sigmoid), 96MB
__device__ float g_sr [(size_t)BTz*Cz];    // FFN gate (sigmoid), fp32
__device__ bf16r g_hb [(size_t)BTz*Cz];    // bf16 LN1 out, later bf16(sr*y)
__device__ bf16r g_h2b[(size_t)BTz*Cz];    // bf16 LN2 out
__device__ bf16r g_kkb[(size_t)BTz*HIDz];  // bf16 FFN hidden
__device__ float g_cA [Bz*Cz*NCHUNK];
__device__ float g_cB [Bz*Cz*NCHUNK];
__device__ float g_a0 [Bz*Cz*NCHUNK];
__device__ float g_b0 [Bz*Cz*NCHUNK];
// packed bf16 weights
__device__ bf16r g_wkvr[Cz*NKVR];          // Wk|Wv|Wr
__device__ bf16r g_wf1 [Cz*NFF1];          // Wk_ffn|Wr_ffn
__device__ bf16r g_wo  [Cz*Cz];
__device__ bf16r g_wvf [HIDz*Cz];

__device__ __forceinline__ bf16r f2b_one(float f) {
    __nv_bfloat16 b = __float2bfloat16(f);
    return *(bf16r*)&b;
}

// ---------------- weight pack / convert ----------------
__global__ void pack_kvr_kernel(const float* __restrict__ Wk,
                                const float* __restrict__ Wv,
                                const float* __restrict__ Wr,
                                bf16r* __restrict__ o)
{
    int i = blockIdx.x * 256 + threadIdx.x;      // Cz*NKVR threads
    int k = i / NKVR, n = i % NKVR;
    float v = (n < 256) ? Wk[k * 256 + n]
            : (n < 512) ? Wv[k * 256 + (n - 256)]
                        : Wr[k * 256 + (n - 512)];
    o[i] = f2b_one(v);
}

__global__ void pack_ffn_kernel(const float* __restrict__ Wkf,
                                const float* __restrict__ Wrf,
                                bf16r* __restrict__ o)
{
    int i = blockIdx.x * 256 + threadIdx.x;      // Cz*NFF1 threads
    int k = i / NFF1, n = i % NFF1;
    float v = (n < 1024) ? Wkf[k * 1024 + n] : Wrf[k * 256 + (n - 1024)];
    o[i] = f2b_one(v);
}

__global__ void f2b_kernel(const float* __restrict__ a, bf16r* __restrict__ o, int n)
{
    int i = blockIdx.x * 256 + threadIdx.x;
    if (i < n) o[i] = f2b_one(a[i]);
}

// ---------------- LayerNorm: one block (256 thr) per token, bf16 out ----------------
__global__ void ln_kernel(const float* __restrict__ x,
                          const float* __restrict__ g,
                          const float* __restrict__ b,
                          bf16r* __restrict__ out)
{
    __shared__ float red[16];
    size_t base = (size_t)blockIdx.x * Cz;
    int c = threadIdx.x;
    float val = x[base + c];
    float s = val, s2 = val * val;
    #pragma unroll
    for (int off = 16; off; off >>= 1) {
        s  += __shfl_xor_sync(0xffffffffu, s,  off);
        s2 += __shfl_xor_sync(0xffffffffu, s2, off);
    }
    int warp = c >> 5, lane = c & 31;
    if (lane == 0) { red[warp] = s; red[8 + warp] = s2; }
    __syncthreads();
    float ts = 0.f, ts2 = 0.f;
    #pragma unroll
    for (int i = 0; i < 8; i++) { ts += red[i]; ts2 += red[8 + i]; }
    float m   = ts  * (1.0f / Cz);
    float var = ts2 * (1.0f / Cz) - m * m;
    out[base + c] = f2b_one((val - m) * rsqrtf(var + 1e-5f) * g[c] + b[c]);
}

// ---------------- async-copy / ldmatrix helpers ----------------
__device__ __forceinline__ void cp16(void* sdst, const void* gsrc) {
    unsigned d = (unsigned)__cvta_generic_to_shared(sdst);
    asm volatile("cp.async.cg.shared.global [%0], [%1], 16;" :: "r"(d), "l"(gsrc));
}
__device__ __forceinline__ void cp_commit() {
    asm volatile("cp.async.commit_group;");
}
__device__ __forceinline__ void ldsm_x4(unsigned& r0, unsigned& r1, unsigned& r2, unsigned& r3,
                                        const void* p) {
    unsigned a = (unsigned)__cvta_generic_to_shared(p);
    asm volatile("ldmatrix.sync.aligned.m8n8.x4.shared.b16 {%0,%1,%2,%3}, [%4];"
                 : "=r"(r0), "=r"(r1), "=r"(r2), "=r"(r3) : "r"(a));
}
__device__ __forceinline__ void ldsm_x4_t(unsigned& r0, unsigned& r1, unsigned& r2, unsigned& r3,
                                          const void* p) {
    unsigned a = (unsigned)__cvta_generic_to_shared(p);
    asm volatile("ldmatrix.sync.aligned.m8n8.x4.trans.shared.b16 {%0,%1,%2,%3}, [%4];"
                 : "=r"(r0), "=r"(r1), "=r"(r2), "=r"(r3) : "r"(a));
}

// ---------------- bf16 tensor-core GEMM: out[M,N] = A[M,K] @ W[K,N] ----------------
// BM=128, BN=64, BK=32, 2-stage cp.async, 256 threads = 8 warps (4x2), warp tile 32x32.
// mode: 0 fp32 plain, 3 fp32 res+acc, 4 fp32 res+gate*acc,
//       5 split: col<1024 -> bf16 relu^2 (out, width 1024); else fp32 sigmoid (out2, width 256)
#define LDA 40
#define LDB 72
__global__ void gemm_bf16_kernel(const bf16r* __restrict__ A,
                                 const bf16r* __restrict__ Bw,
                                 void* __restrict__ outv,
                                 const float* __restrict__ res,
                                 const float* __restrict__ gate,
                                 void* __restrict__ out2v,
                                 int K, int N, int mode)
{
    __shared__ bf16r sA[2][128 * LDA];
    __shared__ bf16r sB[2][32 * LDB];

    int tid  = threadIdx.x;
    int lane = tid & 31;
    int warp = tid >> 5;
    int wm = (warp & 3) * 32;
    int wn = (warp >> 2) * 32;
    int blockRow = blockIdx.x * 128;
    int blockCol = blockIdx.y * 64;

    // per-thread load indices
    int arow0 = tid >> 2;                 // A chunk 0: rows 0..63
    int ach   = (tid & 3) * 8;            // 4 chunks of 8 bf16 per row
    int brow  = tid >> 3;                 // B: 32 rows x 8 chunks
    int bch   = (tid & 7) * 8;

    const bf16r* Ab = A + (size_t)blockRow * K;
    const bf16r* Bb = Bw + blockCol;

    float acc[2][4][4];
    #pragma unroll
    for (int i = 0; i < 2; i++)
        #pragma unroll
        for (int j = 0; j < 4; j++)
            #pragma unroll
            for (int l = 0; l < 4; l++) acc[i][j][l] = 0.f;

    int nk = K >> 5;

    // prefetch tile 0
    {
        cp16(&sA[0][arow0 * LDA + ach],        Ab + (size_t)arow0 * K + ach);
        cp16(&sA[0][(arow0 + 64) * LDA + ach], Ab + (size_t)(arow0 + 64) * K + ach);
        cp16(&sB[0][brow * LDB + bch],         Bb + (size_t)brow * N + bch);
        cp_commit();
    }

    for (int kb = 0; kb < nk; kb++) {
        int buf = kb & 1;
        if (kb + 1 < nk) {
            int ko = (kb + 1) << 5;
            cp16(&sA[buf ^ 1][arow0 * LDA + ach],        Ab + (size_t)arow0 * K + ko + ach);
            cp16(&sA[buf ^ 1][(arow0 + 64) * LDA + ach], Ab + (size_t)(arow0 + 64) * K + ko + ach);
            cp16(&sB[buf ^ 1][brow * LDB + bch],         Bb + (size_t)(ko + brow) * N + bch);
            cp_commit();
            asm volatile("cp.async.wait_group 1;");
        } else {
            asm volatile("cp.async.wait_group 0;");
        }
        __syncthreads();

        #pragma unroll
        for (int k16 = 0; k16 < 2; k16++) {
            int koff = k16 * 16;
            unsigned af[2][4], bfr[2][4];
            #pragma unroll
            for (int sm = 0; sm < 2; sm++)
                ldsm_x4(af[sm][0], af[sm][1], af[sm][2], af[sm][3],
                        &sA[buf][(wm + sm * 16 + (lane & 15)) * LDA + koff + (lane >> 4) * 8]);
            #pragma unroll
            for (int pr = 0; pr < 2; pr++)
                ldsm_x4_t(bfr[pr][0], bfr[pr][1], bfr[pr][2], bfr[pr][3],
                          &sB[buf][(koff + (lane & 15)) * LDB + wn + pr * 16 + (lane >> 4) * 8]);
            #pragma unroll
            for (int sm = 0; sm < 2; sm++)
                #pragma unroll
                for (int sn = 0; sn < 4; sn++) {
                    int pr = sn >> 1, q = (sn & 1) * 2;
                    asm volatile(
                        "mma.sync.aligned.m16n8k16.row.col.f32.bf16.bf16.f32 "
                        "{%0,%1,%2,%3}, {%4,%5,%6,%7}, {%8,%9}, {%0,%1,%2,%3};"
                        : "+f"(acc[sm][sn][0]), "+f"(acc[sm][sn][1]),
                          "+f"(acc[sm][sn][2]), "+f"(acc[sm][sn][3])
                        : "r"(af[sm][0]), "r"(af[sm][1]), "r"(af[sm][2]), "r"(af[sm][3]),
                          "r"(bfr[pr][q]), "r"(bfr[pr][q + 1]));
                }
        }
        __syncthreads();
    }

    // Epilogue
    #pragma unroll
    for (int sm = 0; sm < 2; sm++) {
        #pragma unroll
        for (int sn = 0; sn < 4; sn++) {
            int r0 = blockRow + wm + sm * 16 + (lane >> 2);
            int cc = blockCol + wn + sn * 8 + (lane & 3) * 2;
            #pragma unroll
            for (int half = 0; half < 2; half++) {
                int row = r0 + half * 8;
                float v0 = acc[sm][sn][half * 2 + 0];
                float v1 = acc[sm][sn][half * 2 + 1];
                if (mode == 0) {
                    size_t o = (size_t)row * N + cc;
                    *(float2*)((float*)outv + o) = make_float2(v0, v1);
                } else if (mode == 3) {
                    size_t o = (size_t)row * N + cc;
                    v0 += res[o]; v1 += res[o + 1];
                    *(float2*)((float*)outv + o) = make_float2(v0, v1);
                } else if (mode == 4) {
                    size_t o = (size_t)row * N + cc;
                    v0 = res[o]     + gate[o]     * v0;
                    v1 = res[o + 1] + gate[o + 1] * v1;
                    *(float2*)((float*)outv + o) = make_float2(v0, v1);
                } else { // mode 5 split
                    if (cc < 1024) {
                        float a0 = fmaxf(v0, 0.f), a1 = fmaxf(v1, 0.f);
                        size_t o = (size_t)row * 1024 + cc;
                        unsigned pk = ((unsigned)f2b_one(a1 * a1) << 16) | f2b_one(a0 * a0);
                        *(unsigned*)((bf16r*)outv + o) = pk;
                    } else {
                        size_t o = (size_t)row * 256 + (cc - 1024);
                        float s0 = 1.0f / (1.0f + __expf(-v0));
                        float s1 = 1.0f / (1.0f + __expf(-v1));
                        *(float2*)((float*)out2v + o) = make_float2(s0, s1);
                    }
                }
            }
        }
    }
}

// ---------------- WKV (direct linear recurrence, chunked 3-pass) ----------------
// reads k, v (and pre-sigmoid r in pass3) from packed kvr buffer (stride NKVR)
__global__ void wkv_pass1(const float* __restrict__ kvr, const float* __restrict__ decay)
{
    int b  = blockIdx.x >> 5;
    int ch = blockIdx.x & (NCHUNK - 1);
    int c  = threadIdx.x;
    float w  = decay[c] * (1.0f / Tz);
    float ew = __expf(w);
    size_t base = (size_t)(b * Tz + ch * CHUNK) * NKVR + c;
    float a = 0.f, bb = 0.f;
    #pragma unroll 4
    for (int i = 0; i < CHUNK; i++) {
        float ek = __expf(kvr[base + (size_t)i * NKVR]);
        float vv = kvr[base + 256 + (size_t)i * NKVR];
        a  = fmaf(ew, a,  ek * vv);
        bb = fmaf(ew, bb, ek);
    }
    int o = ch * (Bz * Cz) + b * Cz + c;
    g_cA[o] = a;
    g_cB[o] = bb;
}

__global__ void wkv_pass2(const float* __restrict__ decay)
{
    int idx = blockIdx.x * blockDim.x + threadIdx.x;
    int c = idx & (Cz - 1);
    float w   = decay[c] * (1.0f / Tz);
    float ewL = __expf(w * CHUNK);
    float a = 0.f, bb = 0.f;
    #pragma unroll
    for (int ch = 0; ch < NCHUNK; ch++) {
        int o = ch * (Bz * Cz) + idx;
        g_a0[o] = a;
        g_b0[o] = bb;
        a  = fmaf(ewL, a,  g_cA[o]);
        bb = fmaf(ewL, bb, g_cB[o]);
    }
}

// pass3: y_t, gate with sigmoid(r), emit bf16(sr*y) into hb
__global__ void wkv_pass3(const float* __restrict__ kvr,
                          const float* __restrict__ decay, const float* __restrict__ first,
                          bf16r* __restrict__ hb)
{
    int b  = blockIdx.x >> 5;
    int ch = blockIdx.x & (NCHUNK - 1);
    int c  = threadIdx.x;
    float w  = decay[c] * (1.0f / Tz);
    float u  = first[c] * (1.0f / Tz);
    float ew = __expf(w);
    float eu = __expf(u);
    int co = ch * (Bz * Cz) + b * Cz + c;
    float a  = g_a0[co];
    float bb = g_b0[co];
    int t0 = b * Tz + ch * CHUNK;
    size_t base = (size_t)t0 * NKVR + c;
    size_t ob   = (size_t)t0 * Cz + c;
    #pragma unroll 4
    for (int i = 0; i < CHUNK; i++) {
        float kk = kvr[base + (size_t)i * NKVR];
        float vv = kvr[base + 256 + (size_t)i * NKVR];
        float rr = kvr[base + 512 + (size_t)i * NKVR];
        float ek = __expf(kk);
        float e2 = eu * ek;
        float y  = __fdividef(fmaf(e2, vv, a), bb + e2);
        float sr = 1.0f / (1.0f + __expf(-rr));
        hb[ob + (size_t)i * Cz] = f2b_one(sr * y);
        a  = fmaf(ew, a,  ek * vv);
        bb = fmaf(ew, bb, ek);
    }
}

// ---------------- launch ----------------
extern "C" void kernel_launch(void* const* d_in, const int* in_sizes, int n_in,
                              void* d_out, int out_size)
{
    const float* x      = (const float*)d_in[0];
    const float* Wk     = (const float*)d_in[1];
    const float* Wv     = (const float*)d_in[2];
    const float* Wr     = (const float*)d_in[3];
    const float* Wo     = (const float*)d_in[4];
    const float* Wk_ffn = (const float*)d_in[5];
    const float* Wv_ffn = (const float*)d_in[6];
    const float* Wr_ffn = (const float*)d_in[7];
    const float* g1     = (const float*)d_in[8];
    const float* b1     = (const float*)d_in[9];
    const float* g2     = (const float*)d_in[10];
    const float* b2     = (const float*)d_in[11];
    const float* decay  = (const float*)d_in[12];
    const float* first  = (const float*)d_in[13];
    float* out = (float*)d_out;

    float *kvr, *sr;
    bf16r *hb, *h2b, *kkb, *wkvr, *wf1, *wo, *wvf;
    cudaGetSymbolAddress((void**)&kvr,  g_kvr);
    cudaGetSymbolAddress((void**)&sr,   g_sr);
    cudaGetSymbolAddress((void**)&hb,   g_hb);
    cudaGetSymbolAddress((void**)&h2b,  g_h2b);
    cudaGetSymbolAddress((void**)&kkb,  g_kkb);
    cudaGetSymbolAddress((void**)&wkvr, g_wkvr);
    cudaGetSymbolAddress((void**)&wf1,  g_wf1);
    cudaGetSymbolAddress((void**)&wo,   g_wo);
    cudaGetSymbolAddress((void**)&wvf,  g_wvf);

    // weight pack / convert (small)
    pack_kvr_kernel<<<(Cz * NKVR) / 256, 256>>>(Wk, Wv, Wr, wkvr);
    pack_ffn_kernel<<<(Cz * NFF1) / 256, 256>>>(Wk_ffn, Wr_ffn, wf1);
    f2b_kernel<<<(Cz * Cz)   / 256, 256>>>(Wo,     wo,  Cz * Cz);
    f2b_kernel<<<(HIDz * Cz) / 256, 256>>>(Wv_ffn, wvf, HIDz * Cz);

    dim3 gKVR(BTz / 128, NKVR / 64);   // (256, 12)
    dim3 g256(BTz / 128, Cz   / 64);   // (256, 4)
    dim3 gFF1(BTz / 128, NFF1 / 64);   // (256, 20)

    // ---- SpatialMix ----
    ln_kernel<<<BTz, Cz>>>(x, g1, b1, hb);
    gemm_bf16_kernel<<<gKVR, 256>>>(hb, wkvr, kvr, nullptr, nullptr, nullptr, Cz, NKVR, 0);

    wkv_pass1<<<Bz * NCHUNK, Cz>>>(kvr, decay);
    wkv_pass2<<<Bz, Cz>>>(decay);
    wkv_pass3<<<Bz * NCHUNK, Cz>>>(kvr, decay, first, hb);   // hb := bf16(sr*y)

    gemm_bf16_kernel<<<g256, 256>>>(hb, wo, out, x, nullptr, nullptr, Cz, Cz, 3);

    // ---- ChannelMix ----
    ln_kernel<<<BTz, Cz>>>(out, g2, b2, h2b);
    gemm_bf16_kernel<<<gFF1, 256>>>(h2b, wf1, kkb, nullptr, nullptr, sr, Cz, NFF1, 5);
    gemm_bf16_kernel<<<g256, 256>>>(kkb, wvf, out, out, sr, nullptr, HIDz, Cz, 4);
    (void)in_sizes; (void)n_in; (void)out_size;
}

// round 6
// speedup vs baseline: 3.1869x; 1.0118x over previous
#include <cuda_runtime.h>
#include <cuda_bf16.h>
#include <math.h>

// Problem dims (fixed by the reference)
#define Bz      8
#define Tz      4096
#define Cz      256
#define HIDz    1024
#define BTz     (Bz*Tz)          // 32768 tokens
#define CHUNK   128
#define NCHUNK  (Tz/CHUNK)       // 32
#define NKVR    768              // k|v|r packed width
#define NFF1    1280             // ffn_k|ffn_r packed width

typedef unsigned short bf16r;    // raw bf16 bits

// ---------------- scratch (static __device__, no allocs) ----------------
__device__ float g_kvr[(size_t)BTz*NKVR];  // fp32 k|v|r(pre-sigmoid)
__device__ float g_sr [(size_t)BTz*Cz];    // FFN gate (sigmoid), fp32
__device__ bf16r g_hb [(size_t)BTz*Cz];    // bf16 LN1 out, later bf16(sr*y)
__device__ bf16r g_h2b[(size_t)BTz*Cz];    // bf16 LN2 out
__device__ bf16r g_kkb[(size_t)BTz*HIDz];  // bf16 FFN hidden
__device__ float g_cA [Bz*Cz*NCHUNK];
__device__ float g_cB [Bz*Cz*NCHUNK];
__device__ float g_a0 [Bz*Cz*NCHUNK];
__device__ float g_b0 [Bz*Cz*NCHUNK];
// packed bf16 weights, TRANSPOSED: [N, K] row-major
__device__ bf16r g_wkvr[NKVR*Cz];          // (Wk|Wv|Wr)^T : [768,256]
__device__ bf16r g_wf1 [NFF1*Cz];          // (Wk_ffn|Wr_ffn)^T : [1280,256]
__device__ bf16r g_wo  [Cz*Cz];            // Wo^T : [256,256]
__device__ bf16r g_wvf [Cz*HIDz];          // Wv_ffn^T : [256,1024]

__device__ __forceinline__ bf16r f2b_one(float f) {
    __nv_bfloat16 b = __float2bfloat16(f);
    return *(bf16r*)&b;
}

// ---------------- weight pack / convert (transposed to [N,K]) ----------------
__global__ void pack_kvr_kernel(const float* __restrict__ Wk,
                                const float* __restrict__ Wv,
                                const float* __restrict__ Wr,
                                bf16r* __restrict__ o)
{
    int i = blockIdx.x * 256 + threadIdx.x;      // NKVR*Cz threads
    int n = i / Cz, k = i % Cz;
    float v = (n < 256) ? Wk[k * 256 + n]
            : (n < 512) ? Wv[k * 256 + (n - 256)]
                        : Wr[k * 256 + (n - 512)];
    o[i] = f2b_one(v);
}
__global__ void pack_ffn_kernel(const float* __restrict__ Wkf,
                                const float* __restrict__ Wrf,
                                bf16r* __restrict__ o)
{
    int i = blockIdx.x * 256 + threadIdx.x;      // NFF1*Cz threads
    int n = i / Cz, k = i % Cz;
    float v = (n < 1024) ? Wkf[k * 1024 + n] : Wrf[k * 256 + (n - 1024)];
    o[i] = f2b_one(v);
}
__global__ void packT_kernel(const float* __restrict__ W, bf16r* __restrict__ o,
                             int Kd, int Nd)   // W[Kd,Nd] -> o[Nd,Kd]
{
    int i = blockIdx.x * 256 + threadIdx.x;
    int n = i / Kd, k = i % Kd;
    o[i] = f2b_one(W[(size_t)k * Nd + n]);
}

// ---------------- LayerNorm ----------------
__global__ void ln_kernel(const float* __restrict__ x,
                          const float* __restrict__ g,
                          const float* __restrict__ b,
                          bf16r* __restrict__ out)
{
    __shared__ float red[16];
    size_t base = (size_t)blockIdx.x * Cz;
    int c = threadIdx.x;
    float val = x[base + c];
    float s = val, s2 = val * val;
    #pragma unroll
    for (int off = 16; off; off >>= 1) {
        s  += __shfl_xor_sync(0xffffffffu, s,  off);
        s2 += __shfl_xor_sync(0xffffffffu, s2, off);
    }
    int warp = c >> 5, lane = c & 31;
    if (lane == 0) { red[warp] = s; red[8 + warp] = s2; }
    __syncthreads();
    float ts = 0.f, ts2 = 0.f;
    #pragma unroll
    for (int i = 0; i < 8; i++) { ts += red[i]; ts2 += red[8 + i]; }
    float m   = ts  * (1.0f / Cz);
    float var = ts2 * (1.0f / Cz) - m * m;
    out[base + c] = f2b_one((val - m) * rsqrtf(var + 1e-5f) * g[c] + b[c]);
}

// ---------------- async-copy / ldmatrix helpers ----------------
__device__ __forceinline__ void cp16(void* sdst, const void* gsrc) {
    unsigned d = (unsigned)__cvta_generic_to_shared(sdst);
    asm volatile("cp.async.cg.shared.global [%0], [%1], 16;" :: "r"(d), "l"(gsrc));
}
__device__ __forceinline__ void ldsm_x4(unsigned& r0, unsigned& r1, unsigned& r2, unsigned& r3,
                                        const void* p) {
    unsigned a = (unsigned)__cvta_generic_to_shared(p);
    asm volatile("ldmatrix.sync.aligned.m8n8.x4.shared.b16 {%0,%1,%2,%3}, [%4];"
                 : "=r"(r0), "=r"(r1), "=r"(r2), "=r"(r3) : "r"(a));
}

// ---------------- bf16 tensor-core GEMM: out[M,N] = A[M,K] @ W[K,N]  (BT=W^T [N,K]) --
// BM=128, BN=128, BK=32, 2-stage cp.async, 256 threads = 8 warps (4x2), warp tile 32x64.
// mode: 0 fp32 plain, 3 fp32 res+acc, 4 fp32 res+gate*acc,
//       5 split: col<1024 -> bf16 relu^2 (width 1024); else fp32 sigmoid (out2, width 256)
#define LDT 40      // padded row stride (elements) for 32-wide k tiles
__global__ void __launch_bounds__(256)
gemm_bf16_kernel(const bf16r* __restrict__ A,
                 const bf16r* __restrict__ BT,
                 void* __restrict__ outv,
                 const float* __restrict__ res,
                 const float* __restrict__ gate,
                 void* __restrict__ out2v,
                 int K, int N, int mode)
{
    __shared__ bf16r sA[2][128 * LDT];
    __shared__ bf16r sB[2][128 * LDT];

    int tid  = threadIdx.x;
    int lane = tid & 31;
    int warp = tid >> 5;
    int wm = (warp & 3) * 32;     // warp row offset (4 warps x 32)
    int wn = (warp >> 2) * 64;    // warp col offset (2 warps x 64)
    int blockRow = blockIdx.x * 128;
    int blockCol = blockIdx.y * 128;

    // per-thread load indices: 128 rows x 4 chunks(16B), 512 chunks, 2/thread
    int lrow = tid >> 1;                 // + it*128
    int lch  = (tid & 1) * 16;           // element offset of 16B pair? no: 2 chunks per row half
    // use: idx = tid + it*256; row = idx>>2; ch = (idx&3)*8
    const bf16r* Ab = A  + (size_t)blockRow * K;
    const bf16r* Bb = BT + (size_t)blockCol * K;

    float acc[2][8][4];
    #pragma unroll
    for (int i = 0; i < 2; i++)
        #pragma unroll
        for (int j = 0; j < 8; j++)
            #pragma unroll
            for (int l = 0; l < 4; l++) acc[i][j][l] = 0.f;

    int nk = K >> 5;

    // prefetch tile 0
    #pragma unroll
    for (int it = 0; it < 2; it++) {
        int idx = tid + it * 256;
        int r = idx >> 2, ch = (idx & 3) * 8;
        cp16(&sA[0][r * LDT + ch], Ab + (size_t)r * K + ch);
        cp16(&sB[0][r * LDT + ch], Bb + (size_t)r * K + ch);
    }
    asm volatile("cp.async.commit_group;");

    // ldsm address components
    int a_row = wm + (lane & 15);            // A: 16 rows, two k-halves by lane>>4
    int a_kof = (lane >> 4) * 8;
    int b_grp = lane >> 3;                   // B: 4 groups of 8 lanes
    int b_row = wn + (b_grp >> 1) * 8 + (lane & 7);
    int b_kof = (b_grp & 1) * 8;

    for (int kb = 0; kb < nk; kb++) {
        int buf = kb & 1;
        if (kb + 1 < nk) {
            int ko = (kb + 1) << 5;
            #pragma unroll
            for (int it = 0; it < 2; it++) {
                int idx = tid + it * 256;
                int r = idx >> 2, ch = (idx & 3) * 8;
                cp16(&sA[buf ^ 1][r * LDT + ch], Ab + (size_t)r * K + ko + ch);
                cp16(&sB[buf ^ 1][r * LDT + ch], Bb + (size_t)r * K + ko + ch);
            }
            asm volatile("cp.async.commit_group;");
            asm volatile("cp.async.wait_group 1;");
        } else {
            asm volatile("cp.async.wait_group 0;");
        }
        __syncthreads();

        #pragma unroll
        for (int k16 = 0; k16 < 2; k16++) {
            int koff = k16 * 16;
            unsigned af[2][4], bfr[4][4];
            #pragma unroll
            for (int sm = 0; sm < 2; sm++)
                ldsm_x4(af[sm][0], af[sm][1], af[sm][2], af[sm][3],
                        &sA[buf][(a_row + sm * 16) * LDT + koff + a_kof]);
            #pragma unroll
            for (int pr = 0; pr < 4; pr++)
                ldsm_x4(bfr[pr][0], bfr[pr][1], bfr[pr][2], bfr[pr][3],
                        &sB[buf][(b_row + pr * 16) * LDT + koff + b_kof]);
            #pragma unroll
            for (int sm = 0; sm < 2; sm++)
                #pragma unroll
                for (int sn = 0; sn < 8; sn++) {
                    int pr = sn >> 1, q = (sn & 1) * 2;
                    asm volatile(
                        "mma.sync.aligned.m16n8k16.row.col.f32.bf16.bf16.f32 "
                        "{%0,%1,%2,%3}, {%4,%5,%6,%7}, {%8,%9}, {%0,%1,%2,%3};"
                        : "+f"(acc[sm][sn][0]), "+f"(acc[sm][sn][1]),
                          "+f"(acc[sm][sn][2]), "+f"(acc[sm][sn][3])
                        : "r"(af[sm][0]), "r"(af[sm][1]), "r"(af[sm][2]), "r"(af[sm][3]),
                          "r"(bfr[pr][q]), "r"(bfr[pr][q + 1]));
                }
        }
        __syncthreads();
    }

    // Epilogue
    #pragma unroll
    for (int sm = 0; sm < 2; sm++) {
        #pragma unroll
        for (int sn = 0; sn < 8; sn++) {
            int r0 = blockRow + wm + sm * 16 + (lane >> 2);
            int cc = blockCol + wn + sn * 8 + (lane & 3) * 2;
            #pragma unroll
            for (int half = 0; half < 2; half++) {
                int row = r0 + half * 8;
                float v0 = acc[sm][sn][half * 2 + 0];
                float v1 = acc[sm][sn][half * 2 + 1];
                if (mode == 0) {
                    size_t o = (size_t)row * N + cc;
                    *(float2*)((float*)outv + o) = make_float2(v0, v1);
                } else if (mode == 3) {
                    size_t o = (size_t)row * N + cc;
                    v0 += res[o]; v1 += res[o + 1];
                    *(float2*)((float*)outv + o) = make_float2(v0, v1);
                } else if (mode == 4) {
                    size_t o = (size_t)row * N + cc;
                    v0 = res[o]     + gate[o]     * v0;
                    v1 = res[o + 1] + gate[o + 1] * v1;
                    *(float2*)((float*)outv + o) = make_float2(v0, v1);
                } else { // mode 5 split
                    if (cc < 1024) {
                        float a0 = fmaxf(v0, 0.f), a1 = fmaxf(v1, 0.f);
                        size_t o = (size_t)row * 1024 + cc;
                        unsigned pk = ((unsigned)f2b_one(a1 * a1) << 16) | f2b_one(a0 * a0);
                        *(unsigned*)((bf16r*)outv + o) = pk;
                    } else {
                        size_t o = (size_t)row * 256 + (cc - 1024);
                        float s0 = 1.0f / (1.0f + __expf(-v0));
                        float s1 = 1.0f / (1.0f + __expf(-v1));
                        *(float2*)((float*)out2v + o) = make_float2(s0, s1);
                    }
                }
            }
        }
    }
    (void)lrow; (void)lch;
}

// ---------------- WKV (direct linear recurrence, chunked 3-pass) ----------------
__global__ void wkv_pass1(const float* __restrict__ kvr, const float* __restrict__ decay)
{
    int b  = blockIdx.x >> 5;
    int ch = blockIdx.x & (NCHUNK - 1);
    int c  = threadIdx.x;
    float w  = decay[c] * (1.0f / Tz);
    float ew = __expf(w);
    size_t base = (size_t)(b * Tz + ch * CHUNK) * NKVR + c;
    float a = 0.f, bb = 0.f;
    #pragma unroll 4
    for (int i = 0; i < CHUNK; i++) {
        float ek = __expf(kvr[base + (size_t)i * NKVR]);
        float vv = kvr[base + 256 + (size_t)i * NKVR];
        a  = fmaf(ew, a,  ek * vv);
        bb = fmaf(ew, bb, ek);
    }
    int o = ch * (Bz * Cz) + b * Cz + c;
    g_cA[o] = a;
    g_cB[o] = bb;
}

__global__ void wkv_pass2(const float* __restrict__ decay)
{
    int idx = blockIdx.x * blockDim.x + threadIdx.x;
    int c = idx & (Cz - 1);
    float w   = decay[c] * (1.0f / Tz);
    float ewL = __expf(w * CHUNK);
    float a = 0.f, bb = 0.f;
    #pragma unroll
    for (int ch = 0; ch < NCHUNK; ch++) {
        int o = ch * (Bz * Cz) + idx;
        g_a0[o] = a;
        g_b0[o] = bb;
        a  = fmaf(ewL, a,  g_cA[o]);
        bb = fmaf(ewL, bb, g_cB[o]);
    }
}

__global__ void wkv_pass3(const float* __restrict__ kvr,
                          const float* __restrict__ decay, const float* __restrict__ first,
                          bf16r* __restrict__ hb)
{
    int b  = blockIdx.x >> 5;
    int ch = blockIdx.x & (NCHUNK - 1);
    int c  = threadIdx.x;
    float w  = decay[c] * (1.0f / Tz);
    float u  = first[c] * (1.0f / Tz);
    float ew = __expf(w);
    float eu = __expf(u);
    int co = ch * (Bz * Cz) + b * Cz + c;
    float a  = g_a0[co];
    float bb = g_b0[co];
    int t0 = b * Tz + ch * CHUNK;
    size_t base = (size_t)t0 * NKVR + c;
    size_t ob   = (size_t)t0 * Cz + c;
    #pragma unroll 4
    for (int i = 0; i < CHUNK; i++) {
        float kk = kvr[base + (size_t)i * NKVR];
        float vv = kvr[base + 256 + (size_t)i * NKVR];
        float rr = kvr[base + 512 + (size_t)i * NKVR];
        float ek = __expf(kk);
        float e2 = eu * ek;
        float y  = __fdividef(fmaf(e2, vv, a), bb + e2);
        float sr = 1.0f / (1.0f + __expf(-rr));
        hb[ob + (size_t)i * Cz] = f2b_one(sr * y);
        a  = fmaf(ew, a,  ek * vv);
        bb = fmaf(ew, bb, ek);
    }
}

// ---------------- launch ----------------
extern "C" void kernel_launch(void* const* d_in, const int* in_sizes, int n_in,
                              void* d_out, int out_size)
{
    const float* x      = (const float*)d_in[0];
    const float* Wk     = (const float*)d_in[1];
    const float* Wv     = (const float*)d_in[2];
    const float* Wr     = (const float*)d_in[3];
    const float* Wo     = (const float*)d_in[4];
    const float* Wk_ffn = (const float*)d_in[5];
    const float* Wv_ffn = (const float*)d_in[6];
    const float* Wr_ffn = (const float*)d_in[7];
    const float* g1     = (const float*)d_in[8];
    const float* b1     = (const float*)d_in[9];
    const float* g2     = (const float*)d_in[10];
    const float* b2     = (const float*)d_in[11];
    const float* decay  = (const float*)d_in[12];
    const float* first  = (const float*)d_in[13];
    float* out = (float*)d_out;

    float *kvr, *sr;
    bf16r *hb, *h2b, *kkb, *wkvr, *wf1, *wo, *wvf;
    cudaGetSymbolAddress((void**)&kvr,  g_kvr);
    cudaGetSymbolAddress((void**)&sr,   g_sr);
    cudaGetSymbolAddress((void**)&hb,   g_hb);
    cudaGetSymbolAddress((void**)&h2b,  g_h2b);
    cudaGetSymbolAddress((void**)&kkb,  g_kkb);
    cudaGetSymbolAddress((void**)&wkvr, g_wkvr);
    cudaGetSymbolAddress((void**)&wf1,  g_wf1);
    cudaGetSymbolAddress((void**)&wo,   g_wo);
    cudaGetSymbolAddress((void**)&wvf,  g_wvf);

    // weight pack / convert (transposed to [N,K], small)
    pack_kvr_kernel<<<(NKVR * Cz) / 256, 256>>>(Wk, Wv, Wr, wkvr);
    pack_ffn_kernel<<<(NFF1 * Cz) / 256, 256>>>(Wk_ffn, Wr_ffn, wf1);
    packT_kernel<<<(Cz * Cz)   / 256, 256>>>(Wo,     wo,  Cz,   Cz);
    packT_kernel<<<(HIDz * Cz) / 256, 256>>>(Wv_ffn, wvf, HIDz, Cz);

    dim3 gKVR(BTz / 128, NKVR / 128);   // (256, 6)
    dim3 g256(BTz / 128, Cz   / 128);   // (256, 2)
    dim3 gFF1(BTz / 128, NFF1 / 128);   // (256, 10)

    // ---- SpatialMix ----
    ln_kernel<<<BTz, Cz>>>(x, g1, b1, hb);
    gemm_bf16_kernel<<<gKVR, 256>>>(hb, wkvr, kvr, nullptr, nullptr, nullptr, Cz, NKVR, 0);

    wkv_pass1<<<Bz * NCHUNK, Cz>>>(kvr, decay);
    wkv_pass2<<<Bz, Cz>>>(decay);
    wkv_pass3<<<Bz * NCHUNK, Cz>>>(kvr, decay, first, hb);   // hb := bf16(sr*y)

    gemm_bf16_kernel<<<g256, 256>>>(hb, wo, out, x, nullptr, nullptr, Cz, Cz, 3);

    // ---- ChannelMix ----
    ln_kernel<<<BTz, Cz>>>(out, g2, b2, h2b);
    gemm_bf16_kernel<<<gFF1, 256>>>(h2b, wf1, kkb, nullptr, nullptr, sr, Cz, NFF1, 5);
    gemm_bf16_kernel<<<g256, 256>>>(kkb, wvf, out, out, sr, nullptr, HIDz, Cz, 4);
    (void)in_sizes; (void)n_in; (void)out_size;
}

// round 7
// speedup vs baseline: 3.4529x; 1.0835x over previous
#include <cuda_runtime.h>
#include <cuda_bf16.h>
#include <math.h>

// Problem dims (fixed by the reference)
#define Bz      8
#define Tz      4096
#define Cz      256
#define HIDz    1024
#define BTz     (Bz*Tz)          // 32768 tokens
#define CHUNK   128
#define NCHUNK  (Tz/CHUNK)       // 32
#define NKVR    768              // k|v|r packed width
#define NFF1    1280             // ffn_k|ffn_r packed width

typedef unsigned short bf16r;    // raw bf16 bits

__device__ __forceinline__ bf16r f2b_one(float f) {
    __nv_bfloat16 b = __float2bfloat16(f);
    return *(bf16r*)&b;
}
__device__ __forceinline__ float b2f(bf16r r) {
    return __uint_as_float((unsigned)r << 16);
}

// ---------------- scratch (static __device__, no allocs) ----------------
__device__ bf16r g_kvrb[(size_t)BTz*NKVR]; // bf16 k|v|r(pre-sigmoid), 48MB
__device__ bf16r g_srb [(size_t)BTz*Cz];   // FFN gate (sigmoid), bf16
__device__ bf16r g_hb  [(size_t)BTz*Cz];   // bf16 LN1 out, later bf16(sr*y)
__device__ bf16r g_h2b [(size_t)BTz*Cz];   // bf16 LN2 out
__device__ bf16r g_kkb [(size_t)BTz*HIDz]; // bf16 FFN hidden
__device__ float g_cA [Bz*Cz*NCHUNK];
__device__ float g_cB [Bz*Cz*NCHUNK];
__device__ float g_a0 [Bz*Cz*NCHUNK];
__device__ float g_b0 [Bz*Cz*NCHUNK];
// packed bf16 weights, TRANSPOSED: [N, K] row-major
__device__ bf16r g_wkvr[NKVR*Cz];          // (Wk|Wv|Wr)^T : [768,256]
__device__ bf16r g_wf1 [NFF1*Cz];          // (Wk_ffn|Wr_ffn)^T : [1280,256]
__device__ bf16r g_wo  [Cz*Cz];            // Wo^T : [256,256]
__device__ bf16r g_wvf [Cz*HIDz];          // Wv_ffn^T : [256,1024]

// ---------------- weight packs ----------------
__global__ void pack_kvr_kernel(const float* __restrict__ Wk,
                                const float* __restrict__ Wv,
                                const float* __restrict__ Wr,
                                bf16r* __restrict__ o)
{
    int i = blockIdx.x * 256 + threadIdx.x;      // NKVR*Cz threads
    int n = i / Cz, k = i % Cz;
    float v = (n < 256) ? Wk[k * 256 + n]
            : (n < 512) ? Wv[k * 256 + (n - 256)]
                        : Wr[k * 256 + (n - 512)];
    o[i] = f2b_one(v);
}

// merged: wf1 (327680) | wo (65536) | wvf (262144)
#define PK_F1  (NFF1*Cz)
#define PK_WO  (Cz*Cz)
#define PK_WVF (HIDz*Cz)
__global__ void pack_rest_kernel(const float* __restrict__ Wkf,
                                 const float* __restrict__ Wrf,
                                 const float* __restrict__ Wo,
                                 const float* __restrict__ Wvf,
                                 bf16r* __restrict__ of1,
                                 bf16r* __restrict__ owo,
                                 bf16r* __restrict__ owvf)
{
    int i = blockIdx.x * 256 + threadIdx.x;
    if (i < PK_F1) {
        int n = i / Cz, k = i % Cz;
        float v = (n < 1024) ? Wkf[k * 1024 + n] : Wrf[k * 256 + (n - 1024)];
        of1[i] = f2b_one(v);
    } else if (i < PK_F1 + PK_WO) {
        int j = i - PK_F1;
        int n = j / Cz, k = j % Cz;
        owo[j] = f2b_one(Wo[k * 256 + n]);
    } else {
        int j = i - PK_F1 - PK_WO;
        int n = j / HIDz, k = j % HIDz;
        owvf[j] = f2b_one(Wvf[(size_t)k * 256 + n]);
    }
}

// ---------------- LayerNorm ----------------
__global__ void ln_kernel(const float* __restrict__ x,
                          const float* __restrict__ g,
                          const float* __restrict__ b,
                          bf16r* __restrict__ out)
{
    __shared__ float red[16];
    size_t base = (size_t)blockIdx.x * Cz;
    int c = threadIdx.x;
    float val = x[base + c];
    float s = val, s2 = val * val;
    #pragma unroll
    for (int off = 16; off; off >>= 1) {
        s  += __shfl_xor_sync(0xffffffffu, s,  off);
        s2 += __shfl_xor_sync(0xffffffffu, s2, off);
    }
    int warp = c >> 5, lane = c & 31;
    if (lane == 0) { red[warp] = s; red[8 + warp] = s2; }
    __syncthreads();
    float ts = 0.f, ts2 = 0.f;
    #pragma unroll
    for (int i = 0; i < 8; i++) { ts += red[i]; ts2 += red[8 + i]; }
    float m   = ts  * (1.0f / Cz);
    float var = ts2 * (1.0f / Cz) - m * m;
    out[base + c] = f2b_one((val - m) * rsqrtf(var + 1e-5f) * g[c] + b[c]);
}

// ---------------- async-copy / ldmatrix helpers ----------------
__device__ __forceinline__ void cp16(void* sdst, const void* gsrc) {
    unsigned d = (unsigned)__cvta_generic_to_shared(sdst);
    asm volatile("cp.async.cg.shared.global [%0], [%1], 16;" :: "r"(d), "l"(gsrc));
}
__device__ __forceinline__ void ldsm_x4(unsigned& r0, unsigned& r1, unsigned& r2, unsigned& r3,
                                        const void* p) {
    unsigned a = (unsigned)__cvta_generic_to_shared(p);
    asm volatile("ldmatrix.sync.aligned.m8n8.x4.shared.b16 {%0,%1,%2,%3}, [%4];"
                 : "=r"(r0), "=r"(r1), "=r"(r2), "=r"(r3) : "r"(a));
}

// ---------------- bf16 tensor-core GEMM: out[M,N] = A[M,K] @ W[K,N]  (BT=W^T [N,K]) --
// BM=128, BN=128, BK=32, 2-stage cp.async, 256 threads = 8 warps (4x2), warp tile 32x64.
// mode: 0 bf16 plain, 3 fp32 res+acc, 4 fp32 res + bf16gate*acc,
//       5 split: col<1024 -> bf16 relu^2 (width 1024); else bf16 sigmoid (out2, width 256)
#define LDT 40      // padded row stride (elements)
__global__ void __launch_bounds__(256)
gemm_bf16_kernel(const bf16r* __restrict__ A,
                 const bf16r* __restrict__ BT,
                 void* __restrict__ outv,
                 const float* __restrict__ res,
                 const bf16r* __restrict__ gate,
                 void* __restrict__ out2v,
                 int K, int N, int mode)
{
    __shared__ bf16r sA[2][128 * LDT];
    __shared__ bf16r sB[2][128 * LDT];

    int tid  = threadIdx.x;
    int lane = tid & 31;
    int warp = tid >> 5;
    int wm = (warp & 3) * 32;     // warp row offset (4 warps x 32)
    int wn = (warp >> 2) * 64;    // warp col offset (2 warps x 64)
    int blockRow = blockIdx.x * 128;
    int blockCol = blockIdx.y * 128;

    const bf16r* Ab = A  + (size_t)blockRow * K;
    const bf16r* Bb = BT + (size_t)blockCol * K;

    float acc[2][8][4];
    #pragma unroll
    for (int i = 0; i < 2; i++)
        #pragma unroll
        for (int j = 0; j < 8; j++)
            #pragma unroll
            for (int l = 0; l < 4; l++) acc[i][j][l] = 0.f;

    int nk = K >> 5;

    // prefetch tile 0
    #pragma unroll
    for (int it = 0; it < 2; it++) {
        int idx = tid + it * 256;
        int r = idx >> 2, ch = (idx & 3) * 8;
        cp16(&sA[0][r * LDT + ch], Ab + (size_t)r * K + ch);
        cp16(&sB[0][r * LDT + ch], Bb + (size_t)r * K + ch);
    }
    asm volatile("cp.async.commit_group;");

    // ldsm address components
    int a_row = wm + (lane & 15);
    int a_kof = (lane >> 4) * 8;
    int b_grp = lane >> 3;
    int b_row = wn + (b_grp >> 1) * 8 + (lane & 7);
    int b_kof = (b_grp & 1) * 8;

    for (int kb = 0; kb < nk; kb++) {
        int buf = kb & 1;
        if (kb + 1 < nk) {
            int ko = (kb + 1) << 5;
            #pragma unroll
            for (int it = 0; it < 2; it++) {
                int idx = tid + it * 256;
                int r = idx >> 2, ch = (idx & 3) * 8;
                cp16(&sA[buf ^ 1][r * LDT + ch], Ab + (size_t)r * K + ko + ch);
                cp16(&sB[buf ^ 1][r * LDT + ch], Bb + (size_t)r * K + ko + ch);
            }
            asm volatile("cp.async.commit_group;");
            asm volatile("cp.async.wait_group 1;");
        } else {
            asm volatile("cp.async.wait_group 0;");
        }
        __syncthreads();

        #pragma unroll
        for (int k16 = 0; k16 < 2; k16++) {
            int koff = k16 * 16;
            unsigned af[2][4], bfr[4][4];
            #pragma unroll
            for (int sm = 0; sm < 2; sm++)
                ldsm_x4(af[sm][0], af[sm][1], af[sm][2], af[sm][3],
                        &sA[buf][(a_row + sm * 16) * LDT + koff + a_kof]);
            #pragma unroll
            for (int pr = 0; pr < 4; pr++)
                ldsm_x4(bfr[pr][0], bfr[pr][1], bfr[pr][2], bfr[pr][3],
                        &sB[buf][(b_row + pr * 16) * LDT + koff + b_kof]);
            #pragma unroll
            for (int sm = 0; sm < 2; sm++)
                #pragma unroll
                for (int sn = 0; sn < 8; sn++) {
                    int pr = sn >> 1, q = (sn & 1) * 2;
                    asm volatile(
                        "mma.sync.aligned.m16n8k16.row.col.f32.bf16.bf16.f32 "
                        "{%0,%1,%2,%3}, {%4,%5,%6,%7}, {%8,%9}, {%0,%1,%2,%3};"
                        : "+f"(acc[sm][sn][0]), "+f"(acc[sm][sn][1]),
                          "+f"(acc[sm][sn][2]), "+f"(acc[sm][sn][3])
                        : "r"(af[sm][0]), "r"(af[sm][1]), "r"(af[sm][2]), "r"(af[sm][3]),
                          "r"(bfr[pr][q]), "r"(bfr[pr][q + 1]));
                }
        }
        __syncthreads();
    }

    // Epilogue
    #pragma unroll
    for (int sm = 0; sm < 2; sm++) {
        #pragma unroll
        for (int sn = 0; sn < 8; sn++) {
            int r0 = blockRow + wm + sm * 16 + (lane >> 2);
            int cc = blockCol + wn + sn * 8 + (lane & 3) * 2;
            #pragma unroll
            for (int half = 0; half < 2; half++) {
                int row = r0 + half * 8;
                float v0 = acc[sm][sn][half * 2 + 0];
                float v1 = acc[sm][sn][half * 2 + 1];
                if (mode == 0) {
                    size_t o = (size_t)row * N + cc;
                    unsigned pk = ((unsigned)f2b_one(v1) << 16) | f2b_one(v0);
                    *(unsigned*)((bf16r*)outv + o) = pk;
                } else if (mode == 3) {
                    size_t o = (size_t)row * N + cc;
                    v0 += res[o]; v1 += res[o + 1];
                    *(float2*)((float*)outv + o) = make_float2(v0, v1);
                } else if (mode == 4) {
                    size_t o = (size_t)row * N + cc;
                    unsigned gp = *(const unsigned*)(gate + o);
                    v0 = res[o]     + b2f((bf16r)(gp & 0xFFFFu)) * v0;
                    v1 = res[o + 1] + b2f((bf16r)(gp >> 16))     * v1;
                    *(float2*)((float*)outv + o) = make_float2(v0, v1);
                } else { // mode 5 split
                    if (cc < 1024) {
                        float a0 = fmaxf(v0, 0.f), a1 = fmaxf(v1, 0.f);
                        size_t o = (size_t)row * 1024 + cc;
                        unsigned pk = ((unsigned)f2b_one(a1 * a1) << 16) | f2b_one(a0 * a0);
                        *(unsigned*)((bf16r*)outv + o) = pk;
                    } else {
                        size_t o = (size_t)row * 256 + (cc - 1024);
                        float s0 = 1.0f / (1.0f + __expf(-v0));
                        float s1 = 1.0f / (1.0f + __expf(-v1));
                        unsigned pk = ((unsigned)f2b_one(s1) << 16) | f2b_one(s0);
                        *(unsigned*)((bf16r*)out2v + o) = pk;
                    }
                }
            }
        }
    }
}

// ---------------- WKV (direct linear recurrence, chunked 3-pass, bf16 inputs) -------
__global__ void wkv_pass1(const bf16r* __restrict__ kvr, const float* __restrict__ decay)
{
    int b  = blockIdx.x >> 5;
    int ch = blockIdx.x & (NCHUNK - 1);
    int c  = threadIdx.x;
    float w  = decay[c] * (1.0f / Tz);
    float ew = __expf(w);
    size_t base = (size_t)(b * Tz + ch * CHUNK) * NKVR + c;
    float a = 0.f, bb = 0.f;
    #pragma unroll 4
    for (int i = 0; i < CHUNK; i++) {
        float ek = __expf(b2f(kvr[base + (size_t)i * NKVR]));
        float vv = b2f(kvr[base + 256 + (size_t)i * NKVR]);
        a  = fmaf(ew, a,  ek * vv);
        bb = fmaf(ew, bb, ek);
    }
    int o = ch * (Bz * Cz) + b * Cz + c;
    g_cA[o] = a;
    g_cB[o] = bb;
}

__global__ void wkv_pass2(const float* __restrict__ decay)
{
    int idx = blockIdx.x * blockDim.x + threadIdx.x;
    int c = idx & (Cz - 1);
    float w   = decay[c] * (1.0f / Tz);
    float ewL = __expf(w * CHUNK);
    float a = 0.f, bb = 0.f;
    #pragma unroll
    for (int ch = 0; ch < NCHUNK; ch++) {
        int o = ch * (Bz * Cz) + idx;
        g_a0[o] = a;
        g_b0[o] = bb;
        a  = fmaf(ewL, a,  g_cA[o]);
        bb = fmaf(ewL, bb, g_cB[o]);
    }
}

__global__ void wkv_pass3(const bf16r* __restrict__ kvr,
                          const float* __restrict__ decay, const float* __restrict__ first,
                          bf16r* __restrict__ hb)
{
    int b  = blockIdx.x >> 5;
    int ch = blockIdx.x & (NCHUNK - 1);
    int c  = threadIdx.x;
    float w  = decay[c] * (1.0f / Tz);
    float u  = first[c] * (1.0f / Tz);
    float ew = __expf(w);
    float eu = __expf(u);
    int co = ch * (Bz * Cz) + b * Cz + c;
    float a  = g_a0[co];
    float bb = g_b0[co];
    int t0 = b * Tz + ch * CHUNK;
    size_t base = (size_t)t0 * NKVR + c;
    size_t ob   = (size_t)t0 * Cz + c;
    #pragma unroll 4
    for (int i = 0; i < CHUNK; i++) {
        float kk = b2f(kvr[base + (size_t)i * NKVR]);
        float vv = b2f(kvr[base + 256 + (size_t)i * NKVR]);
        float rr = b2f(kvr[base + 512 + (size_t)i * NKVR]);
        float ek = __expf(kk);
        float e2 = eu * ek;
        float y  = __fdividef(fmaf(e2, vv, a), bb + e2);
        float sr = 1.0f / (1.0f + __expf(-rr));
        hb[ob + (size_t)i * Cz] = f2b_one(sr * y);
        a  = fmaf(ew, a,  ek * vv);
        bb = fmaf(ew, bb, ek);
    }
}

// ---------------- launch ----------------
extern "C" void kernel_launch(void* const* d_in, const int* in_sizes, int n_in,
                              void* d_out, int out_size)
{
    const float* x      = (const float*)d_in[0];
    const float* Wk     = (const float*)d_in[1];
    const float* Wv     = (const float*)d_in[2];
    const float* Wr     = (const float*)d_in[3];
    const float* Wo     = (const float*)d_in[4];
    const float* Wk_ffn = (const float*)d_in[5];
    const float* Wv_ffn = (const float*)d_in[6];
    const float* Wr_ffn = (const float*)d_in[7];
    const float* g1     = (const float*)d_in[8];
    const float* b1     = (const float*)d_in[9];
    const float* g2     = (const float*)d_in[10];
    const float* b2     = (const float*)d_in[11];
    const float* decay  = (const float*)d_in[12];
    const float* first  = (const float*)d_in[13];
    float* out = (float*)d_out;

    bf16r *kvrb, *srb, *hb, *h2b, *kkb, *wkvr, *wf1, *wo, *wvf;
    cudaGetSymbolAddress((void**)&kvrb, g_kvrb);
    cudaGetSymbolAddress((void**)&srb,  g_srb);
    cudaGetSymbolAddress((void**)&hb,   g_hb);
    cudaGetSymbolAddress((void**)&h2b,  g_h2b);
    cudaGetSymbolAddress((void**)&kkb,  g_kkb);
    cudaGetSymbolAddress((void**)&wkvr, g_wkvr);
    cudaGetSymbolAddress((void**)&wf1,  g_wf1);
    cudaGetSymbolAddress((void**)&wo,   g_wo);
    cudaGetSymbolAddress((void**)&wvf,  g_wvf);

    dim3 gKVR(BTz / 128, NKVR / 128);   // (256, 6)
    dim3 g256(BTz / 128, Cz   / 128);   // (256, 2)
    dim3 gFF1(BTz / 128, NFF1 / 128);   // (256, 10)

    // ---- SpatialMix ----  (launch order chosen so #4 = big KVR GEMM for ncu)
    ln_kernel<<<BTz, Cz>>>(x, g1, b1, hb);                                   // 1
    pack_kvr_kernel<<<(NKVR * Cz) / 256, 256>>>(Wk, Wv, Wr, wkvr);           // 2
    pack_rest_kernel<<<(PK_F1 + PK_WO + PK_WVF) / 256, 256>>>(               // 3
        Wk_ffn, Wr_ffn, Wo, Wv_ffn, wf1, wo, wvf);
    gemm_bf16_kernel<<<gKVR, 256>>>(hb, wkvr, kvrb,                          // 4 (profiled)
                                    nullptr, nullptr, nullptr, Cz, NKVR, 0);

    wkv_pass1<<<Bz * NCHUNK, Cz>>>(kvrb, decay);                             // 5
    wkv_pass2<<<Bz, Cz>>>(decay);                                            // 6
    wkv_pass3<<<Bz * NCHUNK, Cz>>>(kvrb, decay, first, hb);                  // 7  hb := bf16(sr*y)

    gemm_bf16_kernel<<<g256, 256>>>(hb, wo, out, x, nullptr, nullptr, Cz, Cz, 3);   // 8

    // ---- ChannelMix ----
    ln_kernel<<<BTz, Cz>>>(out, g2, b2, h2b);                                // 9
    gemm_bf16_kernel<<<gFF1, 256>>>(h2b, wf1, kkb, nullptr, nullptr, srb, Cz, NFF1, 5); // 10
    gemm_bf16_kernel<<<g256, 256>>>(kkb, wvf, out, out, srb, nullptr, HIDz, Cz, 4);     // 11
    (void)in_sizes; (void)n_in; (void)out_size;
}